// round 2
// baseline (speedup 1.0000x reference)
#include <cuda_runtime.h>

// Problem constants (fixed by the dataset)
#define NB 131072   // batch
#define ND 128      // input dim
#define NH 512      // hidden dim
#define NE 2        // experts
#define NO 2        // output dim

// ---------------- scratch (device globals; no allocation allowed) ----------
__device__ int g_cnt[NE];
__device__ int g_idx[NE][NB];

// ---------------- kernel 0: reset counters --------------------------------
__global__ void reset_kernel() {
    if (threadIdx.x < NE) g_cnt[threadIdx.x] = 0;
}

// ---------------- kernel 1: routing + compaction ---------------------------
// 64 samples per CTA, 128 threads. Squared euclidean distance to 2 prototypes,
// argmin (tie -> expert 0, matching jnp.argmin). Block-aggregated atomics.
__global__ __launch_bounds__(128) void route_kernel(const float* __restrict__ x,
                                                    const float* __restrict__ protos) {
    __shared__ float xs[64 * 132];   // padded pitch: conflict-free float4 row reads
    __shared__ float ps[2 * 128];
    __shared__ int   e_sh[64];
    __shared__ int   base_sh[2];

    const int tid = threadIdx.x;
    const int m0  = blockIdx.x * 64;

    for (int i = tid; i < 2 * 128; i += 128) ps[i] = protos[i];

    const float4* x4 = reinterpret_cast<const float4*>(x);
    for (int i = tid; i < 64 * 32; i += 128) {
        int r = i >> 5, c = i & 31;
        float4 v = x4[(size_t)(m0 + r) * 32 + c];
        *reinterpret_cast<float4*>(&xs[r * 132 + c * 4]) = v;
    }
    __syncthreads();

    if (tid < 64) {
        const float4* xr = reinterpret_cast<const float4*>(&xs[tid * 132]);
        const float4* p0 = reinterpret_cast<const float4*>(&ps[0]);
        const float4* p1 = reinterpret_cast<const float4*>(&ps[128]);
        float d0 = 0.f, d1 = 0.f;
        #pragma unroll
        for (int j = 0; j < 32; j++) {
            float4 xv = xr[j]; float4 a = p0[j]; float4 b = p1[j];
            float t;
            t = xv.x - a.x; d0 += t * t;   t = xv.y - a.y; d0 += t * t;
            t = xv.z - a.z; d0 += t * t;   t = xv.w - a.w; d0 += t * t;
            t = xv.x - b.x; d1 += t * t;   t = xv.y - b.y; d1 += t * t;
            t = xv.z - b.z; d1 += t * t;   t = xv.w - b.w; d1 += t * t;
        }
        e_sh[tid] = (d1 < d0) ? 1 : 0;   // tie -> 0 (argmin picks first)
    }
    __syncthreads();

    if (tid == 0) {
        int n0 = 0;
        #pragma unroll 8
        for (int i = 0; i < 64; i++) n0 += (e_sh[i] == 0);
        base_sh[0] = atomicAdd(&g_cnt[0], n0);
        base_sh[1] = atomicAdd(&g_cnt[1], 64 - n0);
    }
    __syncthreads();

    if (tid < 64) {
        int e = e_sh[tid];
        int rank = 0;
        for (int i = 0; i < tid; i++) rank += (e_sh[i] == e);
        g_idx[e][base_sh[e] + rank] = m0 + tid;
    }
}

// ---------------- kernel 2: gathered single-expert MLP ---------------------
// Tile: TM=64 gathered samples, HC=128 hidden rows per chunk (NH/HC=4 chunks).
// 256 threads = 16 tx (h) x 16 ty (m); per thread 4m x 8h register tile.
// Inner product uses packed fp32x2 FMA over k-pairs: accumulator halves hold
// even-k / odd-k partial sums, combined once in the epilogue.
#define TM 64
#define HC 128
#define WP 130          // W chunk smem pitch in floats: lane word-stride 130 ≡ 2 (mod 32) -> conflict-free LDS.64
#define NCHUNK (NH / HC)

__device__ __forceinline__ void ffma2(unsigned long long& d,
                                      unsigned long long a,
                                      unsigned long long b) {
    asm("fma.rn.f32x2 %0, %1, %2, %0;" : "+l"(d) : "l"(a), "l"(b));
}

extern __shared__ float smem_mlp[];

__global__ __launch_bounds__(256, 2) void mlp_kernel(
    const float* __restrict__ x,  const float* __restrict__ w1,
    const float* __restrict__ b1, const float* __restrict__ w2,
    const float* __restrict__ b2, float* __restrict__ out) {

    const int e     = blockIdx.y;
    const int count = g_cnt[e];
    const int tile  = blockIdx.x;
    if (tile * TM >= count) return;

    float* xs   = smem_mlp;               // TM*128 floats
    float* ws   = xs + TM * 128;          // HC*WP floats
    float* b1s  = ws + HC * WP;           // HC
    float* w2s0 = b1s + HC;               // HC
    float* w2s1 = w2s0 + HC;              // HC
    int*   idx_sh = reinterpret_cast<int*>(w2s1 + HC);  // TM

    const int tid = threadIdx.x;
    const int tx  = tid & 15;             // h lanes
    const int ty  = tid >> 4;             // m groups

    if (tid < TM) {
        int pos = tile * TM + tid;
        idx_sh[tid] = (pos < count) ? g_idx[e][pos] : 0;
    }
    __syncthreads();

    // gather x rows (coalesced float4 within each row)
    for (int i = tid; i < TM * 32; i += 256) {
        int r = i >> 5, c = i & 31;
        float4 v = reinterpret_cast<const float4*>(x)[(size_t)idx_sh[r] * 32 + c];
        *reinterpret_cast<float4*>(&xs[r * 128 + c * 4]) = v;
    }

    unsigned long long acc[4][8];
    float o0[4] = {0.f, 0.f, 0.f, 0.f};
    float o1[4] = {0.f, 0.f, 0.f, 0.f};

    const float* w1e = w1 + (size_t)e * NH * ND;

    for (int hc = 0; hc < NCHUNK; hc++) {
        __syncthreads();   // previous chunk fully consumed

        // stage W1 chunk [HC][128] into pitch-WP smem (float2 stores keep 8B align)
        const float2* wsrc = reinterpret_cast<const float2*>(w1e + (size_t)hc * HC * ND);
        for (int i = tid; i < HC * 64; i += 256) {
            int r = i >> 6, c = i & 63;
            float2 v = wsrc[r * 64 + c];
            *reinterpret_cast<float2*>(&ws[r * WP + c * 2]) = v;
        }
        if (tid < HC) {
            int h = hc * HC + tid;
            b1s[tid]  = b1[e * NH + h];
            w2s0[tid] = w2[(e * NO + 0) * NH + h];
            w2s1[tid] = w2[(e * NO + 1) * NH + h];
        }
        __syncthreads();

        #pragma unroll
        for (int mi = 0; mi < 4; mi++)
            #pragma unroll
            for (int hi = 0; hi < 8; hi++)
                acc[mi][hi] = 0ULL;

        const unsigned long long* xr[4];
        const unsigned long long* wr[8];
        #pragma unroll
        for (int mi = 0; mi < 4; mi++)
            xr[mi] = reinterpret_cast<const unsigned long long*>(&xs[(ty * 4 + mi) * 128]);
        #pragma unroll
        for (int hi = 0; hi < 8; hi++)
            wr[hi] = reinterpret_cast<const unsigned long long*>(&ws[(hi * 16 + tx) * WP]);

        #pragma unroll 4
        for (int k = 0; k < 128; k += 4) {
            unsigned long long xa[4], xb[4], wa[8], wb[8];
            const int kp = k >> 1;
            #pragma unroll
            for (int mi = 0; mi < 4; mi++) { xa[mi] = xr[mi][kp]; xb[mi] = xr[mi][kp + 1]; }
            #pragma unroll
            for (int hi = 0; hi < 8; hi++) { wa[hi] = wr[hi][kp]; wb[hi] = wr[hi][kp + 1]; }
            #pragma unroll
            for (int mi = 0; mi < 4; mi++)
                #pragma unroll
                for (int hi = 0; hi < 8; hi++) {
                    ffma2(acc[mi][hi], xa[mi], wa[hi]);
                    ffma2(acc[mi][hi], xb[mi], wb[hi]);
                }
        }

        // fused epilogue: +b1, relu, project through w2 rows 0/1
        #pragma unroll
        for (int hi = 0; hi < 8; hi++) {
            int hl = hi * 16 + tx;
            float bb = b1s[hl], v0 = w2s0[hl], v1 = w2s1[hl];
            #pragma unroll
            for (int mi = 0; mi < 4; mi++) {
                unsigned long long a = acc[mi][hi];
                float s = __uint_as_float((unsigned)a)
                        + __uint_as_float((unsigned)(a >> 32)) + bb;
                s = fmaxf(s, 0.f);
                o0[mi] = fmaf(s, v0, o0[mi]);
                o1[mi] = fmaf(s, v1, o1[mi]);
            }
        }
    }

    // reduce the 16 h-lanes (xor stays inside each 16-lane half-warp)
    #pragma unroll
    for (int mi = 0; mi < 4; mi++) {
        #pragma unroll
        for (int off = 8; off > 0; off >>= 1) {
            o0[mi] += __shfl_xor_sync(0xffffffffu, o0[mi], off);
            o1[mi] += __shfl_xor_sync(0xffffffffu, o1[mi], off);
        }
    }

    if (tx == 0) {
        const float bo0 = b2[e * NO + 0];
        const float bo1 = b2[e * NO + 1];
        #pragma unroll
        for (int mi = 0; mi < 4; mi++) {
            int lpos = ty * 4 + mi;
            int pos  = tile * TM + lpos;
            if (pos < count) {
                int mg = idx_sh[lpos];
                out[(size_t)mg * 2 + 0] = o0[mi] + bo0;
                out[(size_t)mg * 2 + 1] = o1[mi] + bo1;
            }
        }
    }
}

// ---------------- launch ----------------------------------------------------
extern "C" void kernel_launch(void* const* d_in, const int* in_sizes, int n_in,
                              void* d_out, int out_size) {
    const float* x      = (const float*)d_in[0];
    const float* w1     = (const float*)d_in[1];
    const float* b1     = (const float*)d_in[2];
    const float* w2     = (const float*)d_in[3];
    const float* b2     = (const float*)d_in[4];
    const float* protos = (const float*)d_in[5];
    float* out = (float*)d_out;

    const int B = in_sizes[0] / ND;   // 131072

    // dynamic smem: xs + ws + b1s + w2s0 + w2s1 + idx
    const size_t smem_bytes =
        (TM * 128 + HC * WP + 3 * HC) * sizeof(float) + TM * sizeof(int);
    cudaFuncSetAttribute(mlp_kernel, cudaFuncAttributeMaxDynamicSharedMemorySize,
                         (int)smem_bytes);

    reset_kernel<<<1, 32>>>();
    route_kernel<<<B / 64, 128>>>(x, protos);
    dim3 grid((B + TM - 1) / TM, NE);   // over-provisioned; CTAs past count exit
    mlp_kernel<<<grid, 256, smem_bytes>>>(x, w1, b1, w2, b2, out);
}

// round 4
// speedup vs baseline: 2.0814x; 2.0814x over previous
#include <cuda_runtime.h>
#include <cuda_bf16.h>
#include <cstdint>

// Problem constants (fixed by the dataset)
#define NB 131072   // batch
#define ND 128      // input dim
#define NH 512      // hidden dim
#define NE 2        // experts
#define NO 2        // output dim

// ---------------- scratch (device globals; no allocation allowed) ----------
__device__ int g_cnt[NE];
__device__ int g_idx[NE][NB];
// W1 converted: [e][h][ hi bf16 x128 | lo bf16 x128 ]  (512 B per h row)
__device__ __align__(16) __nv_bfloat16 g_w1c[NE * NH * 256];

// ---------------- helpers ---------------------------------------------------
__device__ __forceinline__ uint32_t smem_u32(const void* p) {
    uint32_t a;
    asm("{ .reg .u64 t; cvta.to.shared.u64 t, %1; cvt.u32.u64 %0, t; }"
        : "=r"(a) : "l"(p));
    return a;
}

// fp32 pair -> bf16 hi word + bf16 lo (residual) word
__device__ __forceinline__ void split2(float a, float b, uint32_t& hw, uint32_t& lw) {
    __nv_bfloat16 h0 = __float2bfloat16_rn(a);
    __nv_bfloat16 h1 = __float2bfloat16_rn(b);
    __nv_bfloat16 l0 = __float2bfloat16_rn(a - __bfloat162float(h0));
    __nv_bfloat16 l1 = __float2bfloat16_rn(b - __bfloat162float(h1));
    hw = (uint32_t)__bfloat16_as_ushort(h0) | ((uint32_t)__bfloat16_as_ushort(h1) << 16);
    lw = (uint32_t)__bfloat16_as_ushort(l0) | ((uint32_t)__bfloat16_as_ushort(l1) << 16);
}

__device__ __forceinline__ void ldsm4(uint32_t* r, uint32_t addr) {
    asm volatile("ldmatrix.sync.aligned.m8n8.x4.shared.b16 {%0,%1,%2,%3}, [%4];"
                 : "=r"(r[0]), "=r"(r[1]), "=r"(r[2]), "=r"(r[3]) : "r"(addr));
}

__device__ __forceinline__ void mma16816(float* d, const uint32_t* a,
                                         uint32_t b0, uint32_t b1) {
    asm volatile(
        "mma.sync.aligned.m16n8k16.row.col.f32.bf16.bf16.f32 "
        "{%0,%1,%2,%3}, {%4,%5,%6,%7}, {%8,%9}, {%0,%1,%2,%3};"
        : "+f"(d[0]), "+f"(d[1]), "+f"(d[2]), "+f"(d[3])
        : "r"(a[0]), "r"(a[1]), "r"(a[2]), "r"(a[3]), "r"(b0), "r"(b1));
}

__device__ __forceinline__ void cpasync16(uint32_t dst, const void* src) {
    asm volatile("cp.async.cg.shared.global [%0], [%1], 16;"
                 :: "r"(dst), "l"(src) : "memory");
}

// ---------------- kernel 0: W1 convert (+ counter reset) -------------------
__global__ __launch_bounds__(256) void convw_kernel(const float* __restrict__ w1) {
    if (blockIdx.x == 0 && threadIdx.x < NE) g_cnt[threadIdx.x] = 0;
    int i = blockIdx.x * 256 + threadIdx.x;      // over NE*NH*64 float2
    float2 v = reinterpret_cast<const float2*>(w1)[i];
    uint32_t hw, lw;
    split2(v.x, v.y, hw, lw);
    int row = i >> 6, j = i & 63;
    reinterpret_cast<uint32_t*>(g_w1c)[row * 128 + j]      = hw;
    reinterpret_cast<uint32_t*>(g_w1c)[row * 128 + 64 + j] = lw;
}

// ---------------- kernel 1: routing + compaction ---------------------------
__global__ __launch_bounds__(128) void route_kernel(const float* __restrict__ x,
                                                    const float* __restrict__ protos) {
    __shared__ float xs[64 * 132];
    __shared__ float ps[2 * 128];
    __shared__ int   e_sh[64];
    __shared__ int   base_sh[2];

    const int tid = threadIdx.x;
    const int m0  = blockIdx.x * 64;

    for (int i = tid; i < 2 * 128; i += 128) ps[i] = protos[i];

    const float4* x4 = reinterpret_cast<const float4*>(x);
    for (int i = tid; i < 64 * 32; i += 128) {
        int r = i >> 5, c = i & 31;
        float4 v = x4[(size_t)(m0 + r) * 32 + c];
        *reinterpret_cast<float4*>(&xs[r * 132 + c * 4]) = v;
    }
    __syncthreads();

    if (tid < 64) {
        const float4* xr = reinterpret_cast<const float4*>(&xs[tid * 132]);
        const float4* p0 = reinterpret_cast<const float4*>(&ps[0]);
        const float4* p1 = reinterpret_cast<const float4*>(&ps[128]);
        float d0 = 0.f, d1 = 0.f;
        #pragma unroll
        for (int j = 0; j < 32; j++) {
            float4 xv = xr[j]; float4 a = p0[j]; float4 b = p1[j];
            float t;
            t = xv.x - a.x; d0 += t * t;   t = xv.y - a.y; d0 += t * t;
            t = xv.z - a.z; d0 += t * t;   t = xv.w - a.w; d0 += t * t;
            t = xv.x - b.x; d1 += t * t;   t = xv.y - b.y; d1 += t * t;
            t = xv.z - b.z; d1 += t * t;   t = xv.w - b.w; d1 += t * t;
        }
        e_sh[tid] = (d1 < d0) ? 1 : 0;   // tie -> 0 (argmin picks first)
    }
    __syncthreads();

    if (tid == 0) {
        int n0 = 0;
        #pragma unroll 8
        for (int i = 0; i < 64; i++) n0 += (e_sh[i] == 0);
        base_sh[0] = atomicAdd(&g_cnt[0], n0);
        base_sh[1] = atomicAdd(&g_cnt[1], 64 - n0);
    }
    __syncthreads();

    if (tid < 64) {
        int e = e_sh[tid];
        int rank = 0;
        for (int i = 0; i < tid; i++) rank += (e_sh[i] == e);
        g_idx[e][base_sh[e] + rank] = m0 + tid;
    }
}

// ---------------- kernel 2: HMMA GEMM + fused epilogue ---------------------
// CTA: 128 gathered rows x NH=512. 8 warps = 4(m) x 2(n), warp tile m32 x n64.
// K_eff = 384 via 3 segment passes: (A_hi,B_hi), (A_hi,B_lo), (A_lo,B_hi).
// smem rows are 528 B (512 data + 16 pad) -> conflict-free ldmatrix.
#define PITCH 528
#define SM_A    0
#define SM_W0   (128 * PITCH)                 //  67584
#define SM_W1   (SM_W0 + 128 * PITCH)         // 135168
#define SM_B1   (SM_W1 + 128 * PITCH)         // 202752
#define SM_W20  (SM_B1 + 2048)
#define SM_W21  (SM_W20 + 2048)
#define SM_OUT  (SM_W21 + 2048)               // 128*2 floats
#define SM_IDX  (SM_OUT + 1024)               // 128 ints
#define SM_TOTAL (SM_IDX + 512)               // 210432 bytes

extern __shared__ __align__(1024) unsigned char sm_mma[];

__global__ __launch_bounds__(256, 1) void mma_kernel(
    const float* __restrict__ x,  const float* __restrict__ b1,
    const float* __restrict__ w2, const float* __restrict__ b2,
    float* __restrict__ out) {

    const int c0 = g_cnt[0], c1 = g_cnt[1];
    const int t0 = (c0 + 127) >> 7;
    const int tile = blockIdx.x;
    int e, posbase, count;
    if (tile < t0) { e = 0; posbase = tile * 128; count = c0; }
    else {
        int k = tile - t0;
        if (k >= ((c1 + 127) >> 7)) return;
        e = 1; posbase = k * 128; count = c1;
    }

    const int tid = threadIdx.x;
    const int l   = tid & 31;
    const int w   = tid >> 5;
    const int wm  = w & 3;      // m group (32 rows)
    const int wn  = w >> 2;     // n half (64 cols)

    int*   idx_sh = (int*)(sm_mma + SM_IDX);
    float* b1s    = (float*)(sm_mma + SM_B1);
    float* w20    = (float*)(sm_mma + SM_W20);
    float* w21    = (float*)(sm_mma + SM_W21);
    float* outb   = (float*)(sm_mma + SM_OUT);

    if (tid < 128) {
        int pos = posbase + tid;
        idx_sh[tid] = (pos < count) ? g_idx[e][pos] : g_idx[e][0];
    }
    for (int i = tid; i < NH; i += 256) {
        b1s[i] = b1[e * NH + i];
        w20[i] = w2[(e * NO + 0) * NH + i];
        w21[i] = w2[(e * NO + 1) * NH + i];
    }
    outb[tid] = 0.f;
    __syncthreads();

    const uint32_t smb = smem_u32(sm_mma);
    const __nv_bfloat16* wsrc = g_w1c + (size_t)e * NH * 256;

    // ---- W chunk prefetch (cp.async, 64KB -> 528B-pitch rows) ----
    auto prefetchW = [&](int chunk, int buf) {
        const char* src = (const char*)(wsrc + (size_t)chunk * 128 * 256);
        uint32_t dst = smb + (buf ? SM_W1 : SM_W0);
        #pragma unroll
        for (int k = 0; k < 16; k++) {
            int i = tid + k * 256;                 // 4096 x 16B
            int row = i >> 5, seg = i & 31;
            cpasync16(dst + row * PITCH + seg * 16, src + row * 512 + seg * 16);
        }
        asm volatile("cp.async.commit_group;" ::: "memory");
    };

    prefetchW(0, 0);

    // ---- gather + hi/lo convert A (2 threads per row) ----
    {
        int row = tid >> 1, seg = tid & 1;
        const float4* xr = reinterpret_cast<const float4*>(x)
                           + (size_t)idx_sh[row] * 32 + seg * 16;
        unsigned char* arow = sm_mma + SM_A + row * PITCH;
        #pragma unroll
        for (int j = 0; j < 16; j++) {
            float4 v = xr[j];
            uint32_t h0, l0, h1, l1;
            split2(v.x, v.y, h0, l0);
            split2(v.z, v.w, h1, l1);
            int col = seg * 64 + j * 4;           // bf16 column
            *reinterpret_cast<uint2*>(arow + col * 2)       = make_uint2(h0, h1);
            *reinterpret_cast<uint2*>(arow + 256 + col * 2) = make_uint2(l0, l1);
        }
    }

    prefetchW(1, 1);

    // ---- per-lane ldmatrix base addresses ----
    uint32_t aAddr[2];
    {
        int mrow = wm * 32 + (l & 7) + ((l >> 3) & 1) * 8;
        int koff = (l >= 16) ? 16 : 0;
        aAddr[0] = smb + SM_A + mrow * PITCH + koff;
        aAddr[1] = aAddr[0] + 16 * PITCH;
    }
    uint32_t bOff[4];
    {
        int nr   = (l & 7) + ((l >= 16) ? 8 : 0);
        int koff = ((l >> 3) & 1) * 16;
        #pragma unroll
        for (int nj = 0; nj < 4; nj++)
            bOff[nj] = (uint32_t)((wn * 64 + nj * 16 + nr) * PITCH + koff);
    }

    float o0[4] = {0.f, 0.f, 0.f, 0.f};
    float o1[4] = {0.f, 0.f, 0.f, 0.f};

    const int segA[3] = {0, 0, 256};
    const int segB[3] = {0, 256, 0};

    for (int nt = 0; nt < 4; nt++) {
        const int buf = nt & 1;
        if (nt == 3) asm volatile("cp.async.wait_group 0;" ::: "memory");
        else         asm volatile("cp.async.wait_group 1;" ::: "memory");
        __syncthreads();

        float acc[2][8][4];
        #pragma unroll
        for (int mi = 0; mi < 2; mi++)
            #pragma unroll
            for (int ni = 0; ni < 8; ni++)
                #pragma unroll
                for (int c = 0; c < 4; c++) acc[mi][ni][c] = 0.f;

        const uint32_t wbase = smb + (buf ? SM_W1 : SM_W0);

        #pragma unroll
        for (int s = 0; s < 3; s++) {
            #pragma unroll
            for (int ks = 0; ks < 8; ks++) {
                const int aoff = segA[s] + ks * 32;
                const int boff = segB[s] + ks * 32;
                uint32_t a[2][4], b[4][4];
                ldsm4(a[0], aAddr[0] + aoff);
                ldsm4(a[1], aAddr[1] + aoff);
                #pragma unroll
                for (int nj = 0; nj < 4; nj++)
                    ldsm4(b[nj], wbase + bOff[nj] + boff);
                #pragma unroll
                for (int mi = 0; mi < 2; mi++)
                    #pragma unroll
                    for (int nj = 0; nj < 4; nj++) {
                        mma16816(acc[mi][2 * nj],     a[mi], b[nj][0], b[nj][1]);
                        mma16816(acc[mi][2 * nj + 1], a[mi], b[nj][2], b[nj][3]);
                    }
            }
        }

        __syncthreads();                       // all warps done with W buf
        if (nt < 2) prefetchW(nt + 2, buf);    // overlaps epilogue

        // fused epilogue: +b1, relu, *W2 -> per-lane partial o0/o1
        const int hbase = nt * 128 + wn * 64;
        float bv[16], v0[16], v1[16];
        #pragma unroll
        for (int ni = 0; ni < 8; ni++)
            #pragma unroll
            for (int q = 0; q < 2; q++) {
                int h = hbase + ni * 8 + 2 * (l & 3) + q;
                bv[ni * 2 + q] = b1s[h];
                v0[ni * 2 + q] = w20[h];
                v1[ni * 2 + q] = w21[h];
            }
        #pragma unroll
        for (int mi = 0; mi < 2; mi++)
            #pragma unroll
            for (int ni = 0; ni < 8; ni++)
                #pragma unroll
                for (int c = 0; c < 4; c++) {
                    int t = ni * 2 + (c & 1);
                    float v = fmaxf(acc[mi][ni][c] + bv[t], 0.f);
                    int slot = mi * 2 + (c >> 1);
                    o0[slot] = fmaf(v, v0[t], o0[slot]);
                    o1[slot] = fmaf(v, v1[t], o1[slot]);
                }
    }

    // quad reduce (cols live on l&3), then cross-n-warp via smem atomics
    #pragma unroll
    for (int s = 0; s < 4; s++) {
        o0[s] += __shfl_xor_sync(0xffffffffu, o0[s], 1);
        o0[s] += __shfl_xor_sync(0xffffffffu, o0[s], 2);
        o1[s] += __shfl_xor_sync(0xffffffffu, o1[s], 1);
        o1[s] += __shfl_xor_sync(0xffffffffu, o1[s], 2);
    }
    if ((l & 3) == 0) {
        #pragma unroll
        for (int s = 0; s < 4; s++) {
            int row = wm * 32 + (s >> 1) * 16 + (s & 1) * 8 + (l >> 2);
            atomicAdd(&outb[row * 2 + 0], o0[s]);
            atomicAdd(&outb[row * 2 + 1], o1[s]);
        }
    }
    __syncthreads();

    if (tid < 128) {
        int pos = posbase + tid;
        if (pos < count) {
            int gi = idx_sh[tid];
            out[(size_t)gi * 2 + 0] = outb[tid * 2 + 0] + b2[e * NO + 0];
            out[(size_t)gi * 2 + 1] = outb[tid * 2 + 1] + b2[e * NO + 1];
        }
    }
}

// ---------------- launch ----------------------------------------------------
extern "C" void kernel_launch(void* const* d_in, const int* in_sizes, int n_in,
                              void* d_out, int out_size) {
    const float* x      = (const float*)d_in[0];
    const float* w1     = (const float*)d_in[1];
    const float* b1     = (const float*)d_in[2];
    const float* w2     = (const float*)d_in[3];
    const float* b2     = (const float*)d_in[4];
    const float* protos = (const float*)d_in[5];
    float* out = (float*)d_out;

    static int smem_set = 0;
    if (!smem_set) {
        cudaFuncSetAttribute(mma_kernel, cudaFuncAttributeMaxDynamicSharedMemorySize,
                             SM_TOTAL);
        smem_set = 1;
    }

    convw_kernel<<<NE * NH * 64 / 256, 256>>>(w1);   // also resets counters
    route_kernel<<<NB / 64, 128>>>(x, protos);
    mma_kernel<<<NB / 128 + 2, 256, SM_TOTAL>>>(x, b1, w2, b2, out);
}

// round 5
// speedup vs baseline: 4.3586x; 2.0941x over previous
#include <cuda_runtime.h>
#include <cuda_fp16.h>
#include <cstdint>

// Problem constants (fixed by the dataset)
#define NB 131072   // batch
#define ND 128      // input dim
#define NH 512      // hidden dim
#define NE 2        // experts
#define NO 2        // output dim

// ---------------- scratch (device globals; no allocation allowed) ----------
__device__ int g_cnt[NE];
__device__ int g_idx[NE][NB];
// W1 converted to fp16: [e][h][128 fp16]  (256 B per h row)
__device__ __align__(16) __half g_w1c[NE * NH * 128];

// ---------------- helpers ---------------------------------------------------
__device__ __forceinline__ uint32_t smem_u32(const void* p) {
    uint32_t a;
    asm("{ .reg .u64 t; cvta.to.shared.u64 t, %1; cvt.u32.u64 %0, t; }"
        : "=r"(a) : "l"(p));
    return a;
}

// pack (lo=a, hi=b) as fp16x2 word
__device__ __forceinline__ uint32_t f16x2(float a, float b) {
    uint32_t u;
    asm("cvt.rn.f16x2.f32 %0, %1, %2;" : "=r"(u) : "f"(b), "f"(a));
    return u;
}

__device__ __forceinline__ void ldsm4(uint32_t* r, uint32_t addr) {
    asm volatile("ldmatrix.sync.aligned.m8n8.x4.shared.b16 {%0,%1,%2,%3}, [%4];"
                 : "=r"(r[0]), "=r"(r[1]), "=r"(r[2]), "=r"(r[3]) : "r"(addr));
}

__device__ __forceinline__ void mma16816(float* d, const uint32_t* a,
                                         uint32_t b0, uint32_t b1) {
    asm volatile(
        "mma.sync.aligned.m16n8k16.row.col.f32.f16.f16.f32 "
        "{%0,%1,%2,%3}, {%4,%5,%6,%7}, {%8,%9}, {%0,%1,%2,%3};"
        : "+f"(d[0]), "+f"(d[1]), "+f"(d[2]), "+f"(d[3])
        : "r"(a[0]), "r"(a[1]), "r"(a[2]), "r"(a[3]), "r"(b0), "r"(b1));
}

__device__ __forceinline__ void cpasync16(uint32_t dst, const void* src) {
    asm volatile("cp.async.cg.shared.global [%0], [%1], 16;"
                 :: "r"(dst), "l"(src) : "memory");
}

// ---------------- kernel 0: W1 convert (+ counter reset) -------------------
__global__ __launch_bounds__(256) void convw_kernel(const float* __restrict__ w1) {
    if (blockIdx.x == 0 && threadIdx.x < NE) g_cnt[threadIdx.x] = 0;
    int i = blockIdx.x * 256 + threadIdx.x;      // over NE*NH*64 float2
    float2 v = reinterpret_cast<const float2*>(w1)[i];
    reinterpret_cast<uint32_t*>(g_w1c)[i] = f16x2(v.x, v.y);
}

// ---------------- kernel 1: routing + compaction ---------------------------
__global__ __launch_bounds__(128) void route_kernel(const float* __restrict__ x,
                                                    const float* __restrict__ protos) {
    __shared__ float xs[64 * 132];
    __shared__ float ps[2 * 128];
    __shared__ int   e_sh[64];
    __shared__ int   base_sh[2];

    const int tid = threadIdx.x;
    const int m0  = blockIdx.x * 64;

    for (int i = tid; i < 2 * 128; i += 128) ps[i] = protos[i];

    const float4* x4 = reinterpret_cast<const float4*>(x);
    for (int i = tid; i < 64 * 32; i += 128) {
        int r = i >> 5, c = i & 31;
        float4 v = x4[(size_t)(m0 + r) * 32 + c];
        *reinterpret_cast<float4*>(&xs[r * 132 + c * 4]) = v;
    }
    __syncthreads();

    if (tid < 64) {
        const float4* xr = reinterpret_cast<const float4*>(&xs[tid * 132]);
        const float4* p0 = reinterpret_cast<const float4*>(&ps[0]);
        const float4* p1 = reinterpret_cast<const float4*>(&ps[128]);
        float d0 = 0.f, d1 = 0.f;
        #pragma unroll
        for (int j = 0; j < 32; j++) {
            float4 xv = xr[j]; float4 a = p0[j]; float4 b = p1[j];
            float t;
            t = xv.x - a.x; d0 += t * t;   t = xv.y - a.y; d0 += t * t;
            t = xv.z - a.z; d0 += t * t;   t = xv.w - a.w; d0 += t * t;
            t = xv.x - b.x; d1 += t * t;   t = xv.y - b.y; d1 += t * t;
            t = xv.z - b.z; d1 += t * t;   t = xv.w - b.w; d1 += t * t;
        }
        e_sh[tid] = (d1 < d0) ? 1 : 0;   // tie -> 0 (argmin picks first)
    }
    __syncthreads();

    if (tid == 0) {
        int n0 = 0;
        #pragma unroll 8
        for (int i = 0; i < 64; i++) n0 += (e_sh[i] == 0);
        base_sh[0] = atomicAdd(&g_cnt[0], n0);
        base_sh[1] = atomicAdd(&g_cnt[1], 64 - n0);
    }
    __syncthreads();

    if (tid < 64) {
        int e = e_sh[tid];
        int rank = 0;
        for (int i = 0; i < tid; i++) rank += (e_sh[i] == e);
        g_idx[e][base_sh[e] + rank] = m0 + tid;
    }
}

// ---------------- kernel 2: HMMA GEMM + fused epilogue ---------------------
// CTA: 128 gathered rows x NH=512. 8 warps = 4(m) x 2(n), warp tile m32 x n64.
// fp16 single pass, K=128. smem rows 272 B (256 data + 16 pad).
#define PITCH 272
#define SM_A    0
#define SM_W0   (128 * PITCH)                 //  34816
#define SM_W1   (SM_W0 + 128 * PITCH)         //  69632
#define SM_B1   (SM_W1 + 128 * PITCH)         // 104448
#define SM_W20  (SM_B1 + 2048)                // 106496
#define SM_W21  (SM_W20 + 2048)               // 108544
#define SM_OUT  (SM_W21 + 2048)               // 110592  128*2 floats
#define SM_IDX  (SM_OUT + 1024)               // 111616  128 ints
#define SM_TOTAL (SM_IDX + 512)               // 112128 bytes

extern __shared__ __align__(1024) unsigned char sm_mma[];

__global__ __launch_bounds__(256, 2) void mma_kernel(
    const float* __restrict__ x,  const float* __restrict__ b1,
    const float* __restrict__ w2, const float* __restrict__ b2,
    float* __restrict__ out) {

    const int c0 = g_cnt[0], c1 = g_cnt[1];
    const int t0 = (c0 + 127) >> 7;
    const int tile = blockIdx.x;
    int e, posbase, count;
    if (tile < t0) { e = 0; posbase = tile * 128; count = c0; }
    else {
        int k = tile - t0;
        if (k >= ((c1 + 127) >> 7)) return;
        e = 1; posbase = k * 128; count = c1;
    }

    const int tid = threadIdx.x;
    const int l   = tid & 31;
    const int w   = tid >> 5;
    const int wm  = w & 3;      // m group (32 rows)
    const int wn  = w >> 2;     // n half (64 cols)

    int*   idx_sh = (int*)(sm_mma + SM_IDX);
    float* b1s    = (float*)(sm_mma + SM_B1);
    float* w20    = (float*)(sm_mma + SM_W20);
    float* w21    = (float*)(sm_mma + SM_W21);
    float* outb   = (float*)(sm_mma + SM_OUT);

    if (tid < 128) {
        int pos = posbase + tid;
        idx_sh[tid] = (pos < count) ? g_idx[e][pos] : g_idx[e][0];
    }
    for (int i = tid; i < NH; i += 256) {
        b1s[i] = b1[e * NH + i];
        w20[i] = w2[(e * NO + 0) * NH + i];
        w21[i] = w2[(e * NO + 1) * NH + i];
    }
    outb[tid] = 0.f;
    __syncthreads();

    const uint32_t smb = smem_u32(sm_mma);
    const __half* wsrc = g_w1c + (size_t)e * NH * 128;

    // ---- W chunk prefetch (cp.async, 32KB -> 272B-pitch rows) ----
    auto prefetchW = [&](int chunk, int buf) {
        const char* src = (const char*)(wsrc + (size_t)chunk * 128 * 128);
        uint32_t dst = smb + (buf ? SM_W1 : SM_W0);
        #pragma unroll
        for (int k = 0; k < 8; k++) {
            int i = tid + k * 256;                 // 2048 x 16B
            int row = i >> 4, seg = i & 15;
            cpasync16(dst + row * PITCH + seg * 16, src + row * 256 + seg * 16);
        }
        asm volatile("cp.async.commit_group;" ::: "memory");
    };

    prefetchW(0, 0);

    // ---- gather + fp16 convert A (2 threads per row) ----
    {
        int row = tid >> 1, seg = tid & 1;
        const float4* xr = reinterpret_cast<const float4*>(x)
                           + (size_t)idx_sh[row] * 32 + seg * 16;
        unsigned char* arow = sm_mma + SM_A + row * PITCH;
        #pragma unroll
        for (int j = 0; j < 16; j++) {
            float4 v = xr[j];
            uint32_t w0 = f16x2(v.x, v.y);
            uint32_t w1v = f16x2(v.z, v.w);
            int col = seg * 64 + j * 4;           // fp16 column
            *reinterpret_cast<uint2*>(arow + col * 2) = make_uint2(w0, w1v);
        }
    }

    prefetchW(1, 1);

    // ---- per-lane ldmatrix base addresses ----
    uint32_t aAddr[2];
    {
        int mrow = wm * 32 + (l & 7) + ((l >> 3) & 1) * 8;
        int koff = (l >= 16) ? 16 : 0;
        aAddr[0] = smb + SM_A + mrow * PITCH + koff;
        aAddr[1] = aAddr[0] + 16 * PITCH;
    }
    uint32_t bOff[4];
    {
        int nr   = (l & 7) + ((l >= 16) ? 8 : 0);
        int koff = ((l >> 3) & 1) * 16;
        #pragma unroll
        for (int nj = 0; nj < 4; nj++)
            bOff[nj] = (uint32_t)((wn * 64 + nj * 16 + nr) * PITCH + koff);
    }

    float o0[4] = {0.f, 0.f, 0.f, 0.f};
    float o1[4] = {0.f, 0.f, 0.f, 0.f};

    for (int nt = 0; nt < 4; nt++) {
        const int buf = nt & 1;
        if (nt == 3) asm volatile("cp.async.wait_group 0;" ::: "memory");
        else         asm volatile("cp.async.wait_group 1;" ::: "memory");
        __syncthreads();

        float acc[2][8][4];
        #pragma unroll
        for (int mi = 0; mi < 2; mi++)
            #pragma unroll
            for (int ni = 0; ni < 8; ni++)
                #pragma unroll
                for (int c = 0; c < 4; c++) acc[mi][ni][c] = 0.f;

        const uint32_t wbase = smb + (buf ? SM_W1 : SM_W0);

        #pragma unroll
        for (int ks = 0; ks < 8; ks++) {
            const int off = ks * 32;
            uint32_t a[2][4], b[4][4];
            ldsm4(a[0], aAddr[0] + off);
            ldsm4(a[1], aAddr[1] + off);
            #pragma unroll
            for (int nj = 0; nj < 4; nj++)
                ldsm4(b[nj], wbase + bOff[nj] + off);
            #pragma unroll
            for (int mi = 0; mi < 2; mi++)
                #pragma unroll
                for (int nj = 0; nj < 4; nj++) {
                    mma16816(acc[mi][2 * nj],     a[mi], b[nj][0], b[nj][1]);
                    mma16816(acc[mi][2 * nj + 1], a[mi], b[nj][2], b[nj][3]);
                }
        }

        __syncthreads();                       // all warps done with W buf
        if (nt < 2) prefetchW(nt + 2, buf);    // overlaps epilogue

        // fused epilogue: +b1, relu, *W2 -> per-lane partial o0/o1
        const int hbase = nt * 128 + wn * 64 + 2 * (l & 3);
        #pragma unroll
        for (int ni = 0; ni < 8; ni++) {
            const int h = hbase + ni * 8;
            float bq0 = b1s[h],   bq1 = b1s[h + 1];
            float p00 = w20[h],   p01 = w20[h + 1];
            float p10 = w21[h],   p11 = w21[h + 1];
            #pragma unroll
            for (int mi = 0; mi < 2; mi++)
                #pragma unroll
                for (int c = 0; c < 4; c++) {
                    float v = acc[mi][ni][c] + ((c & 1) ? bq1 : bq0);
                    v = fmaxf(v, 0.f);
                    int slot = mi * 2 + (c >> 1);
                    o0[slot] = fmaf(v, (c & 1) ? p01 : p00, o0[slot]);
                    o1[slot] = fmaf(v, (c & 1) ? p11 : p10, o1[slot]);
                }
        }
    }

    // quad reduce (cols live on l&3), then cross-n-warp via smem atomics
    #pragma unroll
    for (int s = 0; s < 4; s++) {
        o0[s] += __shfl_xor_sync(0xffffffffu, o0[s], 1);
        o0[s] += __shfl_xor_sync(0xffffffffu, o0[s], 2);
        o1[s] += __shfl_xor_sync(0xffffffffu, o1[s], 1);
        o1[s] += __shfl_xor_sync(0xffffffffu, o1[s], 2);
    }
    if ((l & 3) == 0) {
        #pragma unroll
        for (int s = 0; s < 4; s++) {
            int row = wm * 32 + (s >> 1) * 16 + (s & 1) * 8 + (l >> 2);
            atomicAdd(&outb[row * 2 + 0], o0[s]);
            atomicAdd(&outb[row * 2 + 1], o1[s]);
        }
    }
    __syncthreads();

    if (tid < 128) {
        int pos = posbase + tid;
        if (pos < count) {
            int gi = idx_sh[tid];
            out[(size_t)gi * 2 + 0] = outb[tid * 2 + 0] + b2[e * NO + 0];
            out[(size_t)gi * 2 + 1] = outb[tid * 2 + 1] + b2[e * NO + 1];
        }
    }
}

// ---------------- launch ----------------------------------------------------
extern "C" void kernel_launch(void* const* d_in, const int* in_sizes, int n_in,
                              void* d_out, int out_size) {
    const float* x      = (const float*)d_in[0];
    const float* w1     = (const float*)d_in[1];
    const float* b1     = (const float*)d_in[2];
    const float* w2     = (const float*)d_in[3];
    const float* b2     = (const float*)d_in[4];
    const float* protos = (const float*)d_in[5];
    float* out = (float*)d_out;

    static int smem_set = 0;
    if (!smem_set) {
        cudaFuncSetAttribute(mma_kernel, cudaFuncAttributeMaxDynamicSharedMemorySize,
                             SM_TOTAL);
        smem_set = 1;
    }

    convw_kernel<<<NE * NH * 64 / 256, 256>>>(w1);   // also resets counters
    route_kernel<<<NB / 64, 128>>>(x, protos);
    mma_kernel<<<NB / 128 + 2, 256, SM_TOTAL>>>(x, b1, w2, b2, out);
}